// round 5
// baseline (speedup 1.0000x reference)
#include <cuda_runtime.h>
#include <cstdint>
#include <math.h>

// Problem constants
#define DIMC  512
#define NH    8
#define HD    64
#define NB    8
#define NSEQ  1024
#define QK_SCALE 0.125f   // HEAD_DIM^-0.5

// Scratch (device globals — no allocation allowed)
__device__ float g_q[NB * NH * NSEQ * HD];     // [B,H,N,D], tf32-rounded, pre-scaled
__device__ float g_k[NB * NH * NSEQ * HD];     // [B,H,N,D], tf32-rounded
__device__ float g_v[NB * NH * NSEQ * HD];     // [B,H,N,D], tf32-rounded
__device__ float g_attn[NB * NSEQ * DIMC];     // [B,N,C] attention output (f32)

// ===========================================================================
// mma.sync tf32 helpers (sm_80+ PTX — no 'a'-gated features)
// ===========================================================================
__device__ __forceinline__ uint32_t f2tf(float f) {
    uint32_t r;
    asm("cvt.rna.tf32.f32 %0, %1;" : "=r"(r) : "f"(f));
    return r;
}
// D(16x8,f32) += A(16x8,tf32,row) * B(8x8,tf32,col)
__device__ __forceinline__ void mma8(float* d, const uint32_t* a, uint32_t b0, uint32_t b1) {
    asm volatile(
        "mma.sync.aligned.m16n8k8.row.col.f32.tf32.tf32.f32 "
        "{%0,%1,%2,%3}, {%4,%5,%6,%7}, {%8,%9}, {%0,%1,%2,%3};"
        : "+f"(d[0]), "+f"(d[1]), "+f"(d[2]), "+f"(d[3])
        : "r"(a[0]), "r"(a[1]), "r"(a[2]), "r"(a[3]), "r"(b0), "r"(b1));
}
// pair-permute: element with k-index k stored at column perm(k) so that the
// fragment pair (k, k+4) is contiguous -> one LDS.64 per fragment pair.
__device__ __forceinline__ int permk(int k) {
    return (k & ~7) | ((k & 3) << 1) | ((k >> 2) & 1);
}

// ===========================================================================
// Projection GEMM (tf32 mma): C[128,128] tile of  A[M,512] . W[N,512]^T
// mode 0: A = x, epilogue scatters tf32-rounded q(*0.125)/k/v into g_q/g_k/g_v
// mode 1: A = g_attn, epilogue adds bias, writes f32 Out
// 256 threads, 8 warps in 2x4 (warp tile 64x32), BK=32 double-buffered.
// ===========================================================================
#define GP 40                              // smem pitch (32 k + 8 pad floats)
#define GEMM_SMEM (4 * 128 * GP * 4)       // 2 bufs x (A+B) = 81920 B

__global__ __launch_bounds__(256) void mma_gemm(const float* __restrict__ Ain,
                                                const float* __restrict__ Wp,
                                                const float* __restrict__ Bvec,
                                                float* __restrict__ Out,
                                                int mode) {
    extern __shared__ float sm[];
    const int tid = threadIdx.x, wid = tid >> 5, lane = tid & 31;
    const int g = lane >> 2, th = lane & 3;
    const int wm = wid >> 2, wn = wid & 3;
    const int bm = blockIdx.x * 128, bn = blockIdx.y * 128;
    const float* Ap = mode ? (const float*)g_attn : Ain;

    const int lr = tid >> 1;              // 0..127
    const int lkb = (tid & 1) * 16;       // 0 or 16
    const float* ga = Ap + (size_t)(bm + lr) * 512 + lkb;
    const float* gb = Wp + (size_t)(bn + lr) * 512 + lkb;

    float4 fa[4], fb[4];
#pragma unroll
    for (int p = 0; p < 4; p++) { fa[p] = *(const float4*)(ga + 4 * p); fb[p] = *(const float4*)(gb + 4 * p); }

    float acc[4][4][4];
#pragma unroll
    for (int i = 0; i < 4; i++)
#pragma unroll
        for (int j = 0; j < 4; j++)
#pragma unroll
            for (int q = 0; q < 4; q++) acc[i][j][q] = 0.0f;

    for (int i = 0; i < 16; i++) {
        float* A = sm + (i & 1) * 2 * 128 * GP;
        float* B = A + 128 * GP;
        // store chunk i (tf32-rounded) into smem, pair-permuted
#pragma unroll
        for (int p = 0; p < 4; p++) {
            int k0 = lkb + 4 * p;
            int cb = (k0 & ~7) + ((k0 >> 2) & 1);
            float* ar = A + lr * GP + cb;
            ar[0] = __uint_as_float(f2tf(fa[p].x)); ar[2] = __uint_as_float(f2tf(fa[p].y));
            ar[4] = __uint_as_float(f2tf(fa[p].z)); ar[6] = __uint_as_float(f2tf(fa[p].w));
            float* br = B + lr * GP + cb;
            br[0] = __uint_as_float(f2tf(fb[p].x)); br[2] = __uint_as_float(f2tf(fb[p].y));
            br[4] = __uint_as_float(f2tf(fb[p].z)); br[6] = __uint_as_float(f2tf(fb[p].w));
        }
        __syncthreads();
        if (i < 15) {
            int k0 = (i + 1) * 32;
#pragma unroll
            for (int p = 0; p < 4; p++) {
                fa[p] = *(const float4*)(ga + k0 + 4 * p);
                fb[p] = *(const float4*)(gb + k0 + 4 * p);
            }
        }
        // compute chunk i
#pragma unroll
        for (int s = 0; s < 4; s++) {
            uint32_t Af[4][4];
#pragma unroll
            for (int ma = 0; ma < 4; ma++) {
                float2 lo = *(float2*)&A[(wm * 64 + ma * 16 + g) * GP + 8 * s + 2 * th];
                float2 hi = *(float2*)&A[(wm * 64 + ma * 16 + g + 8) * GP + 8 * s + 2 * th];
                Af[ma][0] = __float_as_uint(lo.x); Af[ma][1] = __float_as_uint(hi.x);
                Af[ma][2] = __float_as_uint(lo.y); Af[ma][3] = __float_as_uint(hi.y);
            }
#pragma unroll
            for (int na = 0; na < 4; na++) {
                float2 bv = *(float2*)&B[(wn * 32 + na * 8 + g) * GP + 8 * s + 2 * th];
                uint32_t b0 = __float_as_uint(bv.x), b1 = __float_as_uint(bv.y);
#pragma unroll
                for (int ma = 0; ma < 4; ma++) mma8(acc[ma][na], Af[ma], b0, b1);
            }
        }
        __syncthreads();
    }

    // Epilogue: D frag rows (r, r+8), cols (c, c+1)
#pragma unroll
    for (int ma = 0; ma < 4; ma++) {
#pragma unroll
        for (int na = 0; na < 4; na++) {
            int r0 = bm + wm * 64 + ma * 16 + g;
            int cg = bn + wn * 32 + na * 8 + 2 * th;
#pragma unroll
            for (int e = 0; e < 2; e++) {
                int r = r0 + e * 8;
                float v0 = acc[ma][na][2 * e], v1 = acc[ma][na][2 * e + 1];
                if (mode == 0) {
                    int bb = r >> 10, n = r & 1023;
                    int which = cg >> 9, hh = (cg >> 6) & 7, dd = cg & 63;
                    size_t off = (((size_t)(bb * NH + hh)) * NSEQ + n) * HD + dd;
                    float2 o;
                    if (which == 0) {
                        o.x = __uint_as_float(f2tf(v0 * QK_SCALE));
                        o.y = __uint_as_float(f2tf(v1 * QK_SCALE));
                        *(float2*)(g_q + off) = o;
                    } else if (which == 1) {
                        o.x = __uint_as_float(f2tf(v0)); o.y = __uint_as_float(f2tf(v1));
                        *(float2*)(g_k + off) = o;
                    } else {
                        o.x = __uint_as_float(f2tf(v0)); o.y = __uint_as_float(f2tf(v1));
                        *(float2*)(g_v + off) = o;
                    }
                } else {
                    float2 bv = *(const float2*)(Bvec + cg);
                    float2 o; o.x = v0 + bv.x; o.y = v1 + bv.y;
                    *(float2*)(Out + (size_t)r * 512 + cg) = o;
                }
            }
        }
    }
}

// ===========================================================================
// Flash attention, tf32 mma. Grid (8 qt, 8 h, 8 b), 256 threads, 8 warps.
// q-tile 128; each warp owns 16 q-rows and the full 64-wide kv tile so the
// softmax row reduction stays inside one warp (quad shuffles).
// P -> A-fragment relayout for P.V is done with quad shfl (no smem P).
// ===========================================================================
#define AP 72
#define ATT_SMEM (2 * 64 * AP * 4)   // Ks + Vt = 36864 B

__global__ __launch_bounds__(256) void attn_mma(const float* __restrict__ bias) {
    extern __shared__ float sm[];
    float* Ks = sm;             // [kv=64][perm d], pitch 72
    float* Vt = sm + 64 * AP;   // [d=64][perm kv], pitch 72

    const int qt = blockIdx.x, h = blockIdx.y, b = blockIdx.z;
    const int tid = threadIdx.x, wid = tid >> 5, lane = tid & 31;
    const int g = lane >> 2, th = lane & 3;

    const size_t bh = (size_t)(b * NH + h);
    const float* Kg = g_k + bh * NSEQ * HD;
    const float* Vg = g_v + bh * NSEQ * HD;

    // Q fragments (g_q already tf32-rounded and *QK_SCALE): load once
    const int m0 = wid * 16;
    const int qrow = qt * 128 + m0 + g;
    const float* Q0 = g_q + (bh * NSEQ + qrow) * HD;
    const float* Q1 = Q0 + 8 * HD;
    uint32_t qa[8][4];
#pragma unroll
    for (int s = 0; s < 8; s++) {
        qa[s][0] = __float_as_uint(Q0[8 * s + th]);
        qa[s][1] = __float_as_uint(Q1[8 * s + th]);
        qa[s][2] = __float_as_uint(Q0[8 * s + th + 4]);
        qa[s][3] = __float_as_uint(Q1[8 * s + th + 4]);
    }

    float O[8][4];
#pragma unroll
    for (int na = 0; na < 8; na++)
#pragma unroll
        for (int q = 0; q < 4; q++) O[na][q] = 0.0f;
    float mrow[2] = {-INFINITY, -INFINITY};
    float lrow[2] = {0.0f, 0.0f};

    const int lr4 = tid >> 2;            // 0..63
    const int lc4 = (tid & 3) * 16;      // 0,16,32,48
    const int pk = (lr4 & ~7) | ((lr4 & 3) << 1) | ((lr4 >> 2) & 1);  // perm(kv)

    for (int t = 0; t < 16; t++) {
        __syncthreads();   // prev tile's reads of Ks/Vt complete
        // K tile: [kv][d] -> Ks[kv][perm(d)]
        const float* kp = Kg + (size_t)(t * 64 + lr4) * 64 + lc4;
        const float* vp = Vg + (size_t)(t * 64 + lr4) * 64 + lc4;
#pragma unroll
        for (int p = 0; p < 4; p++) {
            float4 k4 = *(const float4*)(kp + 4 * p);
            int d0 = lc4 + 4 * p;
            int cb = (d0 & ~7) + ((d0 >> 2) & 1);
            float* kr = Ks + lr4 * AP + cb;
            kr[0] = k4.x; kr[2] = k4.y; kr[4] = k4.z; kr[6] = k4.w;
            // V tile transposed: [kv][d] -> Vt[d][perm(kv)]
            float4 v4 = *(const float4*)(vp + 4 * p);
            Vt[(d0 + 0) * AP + pk] = v4.x;
            Vt[(d0 + 1) * AP + pk] = v4.y;
            Vt[(d0 + 2) * AP + pk] = v4.z;
            Vt[(d0 + 3) * AP + pk] = v4.w;
        }
        __syncthreads();

        // S = Q K^T  (16 x 64 per warp)
        float S[8][4];
#pragma unroll
        for (int na = 0; na < 8; na++)
#pragma unroll
            for (int q = 0; q < 4; q++) S[na][q] = 0.0f;
#pragma unroll
        for (int s = 0; s < 8; s++) {
#pragma unroll
            for (int na = 0; na < 8; na++) {
                float2 bv = *(float2*)&Ks[(na * 8 + g) * AP + 8 * s + 2 * th];
                mma8(S[na], qa[s], __float_as_uint(bv.x), __float_as_uint(bv.y));
            }
        }

        // + rpe_bias[h, qrow, kcol]
        const float* bp0 = bias + ((size_t)h * NSEQ + qrow) * NSEQ + t * 64 + 2 * th;
        const float* bp1 = bp0 + 8 * NSEQ;
#pragma unroll
        for (int na = 0; na < 8; na++) {
            float2 b0v = *(const float2*)(bp0 + na * 8);
            float2 b1v = *(const float2*)(bp1 + na * 8);
            S[na][0] += b0v.x; S[na][1] += b0v.y;
            S[na][2] += b1v.x; S[na][3] += b1v.y;
        }

        // online softmax; rows e=0 -> (S[.][0],S[.][1]),  e=1 -> (S[.][2],S[.][3])
#pragma unroll
        for (int e = 0; e < 2; e++) {
            float mx = -INFINITY;
#pragma unroll
            for (int na = 0; na < 8; na++)
                mx = fmaxf(mx, fmaxf(S[na][2 * e], S[na][2 * e + 1]));
            mx = fmaxf(mx, __shfl_xor_sync(0xffffffffu, mx, 1));
            mx = fmaxf(mx, __shfl_xor_sync(0xffffffffu, mx, 2));
            float mn = fmaxf(mrow[e], mx);
            float al = __expf(mrow[e] - mn);
            mrow[e] = mn;
            float ls = 0.0f;
#pragma unroll
            for (int na = 0; na < 8; na++) {
                S[na][2 * e]     = __expf(S[na][2 * e] - mn);
                S[na][2 * e + 1] = __expf(S[na][2 * e + 1] - mn);
                ls += S[na][2 * e] + S[na][2 * e + 1];
            }
            ls += __shfl_xor_sync(0xffffffffu, ls, 1);
            ls += __shfl_xor_sync(0xffffffffu, ls, 2);
            lrow[e] = lrow[e] * al + ls;
#pragma unroll
            for (int na = 0; na < 8; na++) { O[na][2 * e] *= al; O[na][2 * e + 1] *= al; }
        }

        // round P to tf32 in place (stored as float bits)
#pragma unroll
        for (int na = 0; na < 8; na++)
#pragma unroll
            for (int q = 0; q < 4; q++) S[na][q] = __uint_as_float(f2tf(S[na][q]));

        // O += P V : re-fragment P via quad shuffles (D-frag -> A-frag)
        const int src0 = (lane & ~3) | (th >> 1);
        const int src2 = src0 + 2;
        const bool odd = (th & 1);
#pragma unroll
        for (int s = 0; s < 8; s++) {
            float x0 = __shfl_sync(0xffffffffu, S[s][0], src0);
            float x1 = __shfl_sync(0xffffffffu, S[s][1], src0);
            float y0 = __shfl_sync(0xffffffffu, S[s][2], src0);
            float y1 = __shfl_sync(0xffffffffu, S[s][3], src0);
            float z0 = __shfl_sync(0xffffffffu, S[s][0], src2);
            float z1 = __shfl_sync(0xffffffffu, S[s][1], src2);
            float w0 = __shfl_sync(0xffffffffu, S[s][2], src2);
            float w1 = __shfl_sync(0xffffffffu, S[s][3], src2);
            uint32_t a[4];
            a[0] = __float_as_uint(odd ? x1 : x0);   // P[g   ][8s+th]
            a[1] = __float_as_uint(odd ? y1 : y0);   // P[g+8 ][8s+th]
            a[2] = __float_as_uint(odd ? z1 : z0);   // P[g   ][8s+th+4]
            a[3] = __float_as_uint(odd ? w1 : w0);   // P[g+8 ][8s+th+4]
#pragma unroll
            for (int na = 0; na < 8; na++) {
                float2 bv = *(float2*)&Vt[(na * 8 + g) * AP + 8 * s + 2 * th];
                mma8(O[na], a, __float_as_uint(bv.x), __float_as_uint(bv.y));
            }
        }
    }

    // normalize + write to g_attn [B,N,C]
    const float i0 = 1.0f / lrow[0];
    const float i1 = 1.0f / lrow[1];
    float* ob = g_attn + ((size_t)b * NSEQ + qrow) * DIMC + h * 64 + 2 * th;
#pragma unroll
    for (int na = 0; na < 8; na++) {
        float2 o0; o0.x = O[na][0] * i0; o0.y = O[na][1] * i0;
        *(float2*)(ob + na * 8) = o0;
        float2 o1; o1.x = O[na][2] * i1; o1.y = O[na][3] * i1;
        *(float2*)(ob + (size_t)8 * DIMC + na * 8) = o1;
    }
}

// ---------------------------------------------------------------------------
extern "C" void kernel_launch(void* const* d_in, const int* in_sizes, int n_in,
                              void* d_out, int out_size) {
    const float* x      = (const float*)d_in[0];  // [8,1024,512]
    const float* rpe    = (const float*)d_in[1];  // [1,8,1024,1024]
    const float* qkv_w  = (const float*)d_in[2];  // [1536,512]
    const float* proj_w = (const float*)d_in[3];  // [512,512]
    const float* proj_b = (const float*)d_in[4];  // [512]
    float* out = (float*)d_out;                   // [8,1024,512]

    cudaFuncSetAttribute(mma_gemm, cudaFuncAttributeMaxDynamicSharedMemorySize, GEMM_SMEM);

    // QKV projection: M=8192, N=1536
    mma_gemm<<<dim3(64, 12), 256, GEMM_SMEM>>>(x, qkv_w, nullptr, nullptr, 0);

    // Attention
    attn_mma<<<dim3(8, 8, 8), 256, ATT_SMEM>>>(rpe);

    // Output projection: M=8192, N=512
    mma_gemm<<<dim3(64, 4), 256, GEMM_SMEM>>>(nullptr, proj_w, proj_b, out, 1);
}

// round 7
// speedup vs baseline: 1.1353x; 1.1353x over previous
#include <cuda_runtime.h>
#include <cstdint>
#include <math.h>

#define DIMC  512
#define NH    8
#define HD    64
#define NB    8
#define NSEQ  1024
#define QK_SCALE 0.125f

__device__ float g_q[NB * NH * NSEQ * HD];
__device__ float g_k[NB * NH * NSEQ * HD];
__device__ float g_v[NB * NH * NSEQ * HD];
__device__ float g_attn[NB * NSEQ * DIMC];

__device__ __forceinline__ uint32_t f2tf(float f) {
    uint32_t r;
    asm("cvt.rna.tf32.f32 %0, %1;" : "=r"(r) : "f"(f));
    return r;
}
__device__ __forceinline__ void mma8(float* d, const uint32_t* a, uint32_t b0, uint32_t b1) {
    asm volatile(
        "mma.sync.aligned.m16n8k8.row.col.f32.tf32.tf32.f32 "
        "{%0,%1,%2,%3}, {%4,%5,%6,%7}, {%8,%9}, {%0,%1,%2,%3};"
        : "+f"(d[0]), "+f"(d[1]), "+f"(d[2]), "+f"(d[3])
        : "r"(a[0]), "r"(a[1]), "r"(a[2]), "r"(a[3]), "r"(b0), "r"(b1));
}

// ===========================================================================
// GEMM: C[128,128] tile of A[M,512] . W[N,512]^T.  128 thr, 4 warps (2x2),
// warp tile 64x64, BK=32 double-buffered.  Pair (8s+j, 8s+j+4) of row r at
// slot r*GP + 8s + 2*((j + (r>>2))&3)   (rotation -> 2-way max conflicts).
// ===========================================================================
#define GP 40
#define GEMM_SMEM (2 * 2 * 128 * GP * 4)   // 81920 B

__global__ __launch_bounds__(128, 2) void mma_gemm(const float* __restrict__ Ain,
                                                   const float* __restrict__ Wp,
                                                   const float* __restrict__ Bvec,
                                                   float* __restrict__ Out,
                                                   int mode) {
    extern __shared__ float sm[];
    const int tid = threadIdx.x, wid = tid >> 5, lane = tid & 31;
    const int g = lane >> 2, th = lane & 3;
    const int wm = wid >> 1, wn = wid & 1;
    const int bm = blockIdx.x * 128, bn = blockIdx.y * 128;
    const float* Ap = mode ? (const float*)g_attn : Ain;

    // loader: this thread owns row r of both A and B tiles
    const int r = tid;
    const int rot = (r >> 2) & 3;
    const float* ga = Ap + (size_t)(bm + r) * 512;
    const float* gb = Wp + (size_t)(bn + r) * 512;

    // reader offsets (rotation folded in; +8*s per k-step)
    int offA0[4], offA1[4], offB[8];
#pragma unroll
    for (int ma = 0; ma < 4; ma++) {
        int ra = wm * 64 + ma * 16 + g;
        offA0[ma] = ra * GP + 2 * ((th + (ra >> 2)) & 3);
        int rb = ra + 8;
        offA1[ma] = rb * GP + 2 * ((th + (rb >> 2)) & 3);
    }
#pragma unroll
    for (int nb = 0; nb < 8; nb++) {
        int rc = wn * 64 + nb * 8 + g;
        offB[nb] = rc * GP + 2 * ((th + (rc >> 2)) & 3);
    }

    float acc[4][8][4];
#pragma unroll
    for (int i = 0; i < 4; i++)
#pragma unroll
        for (int j = 0; j < 8; j++)
#pragma unroll
            for (int q = 0; q < 4; q++) acc[i][j][q] = 0.0f;

    float4 fa[8], fb[8];
#pragma unroll
    for (int p = 0; p < 8; p++) { fa[p] = *(const float4*)(ga + 4 * p); fb[p] = *(const float4*)(gb + 4 * p); }

    // store staged chunk into buffer `buf`
    auto store_chunk = [&](int buf) {
        float* Aw = sm + buf * 2 * 128 * GP + r * GP;
        float* Bw = Aw + 128 * GP;
        const float* sa = (const float*)fa;
        const float* sb = (const float*)fb;
#pragma unroll
        for (int s = 0; s < 4; s++) {
#pragma unroll
            for (int j = 0; j < 4; j++) {
                int sl = 8 * s + 2 * ((j + rot) & 3);
                float2 pa, pb;
                pa.x = __uint_as_float(f2tf(sa[8 * s + j]));
                pa.y = __uint_as_float(f2tf(sa[8 * s + 4 + j]));
                pb.x = __uint_as_float(f2tf(sb[8 * s + j]));
                pb.y = __uint_as_float(f2tf(sb[8 * s + 4 + j]));
                *(float2*)(Aw + sl) = pa;
                *(float2*)(Bw + sl) = pb;
            }
        }
    };

    store_chunk(0);
    __syncthreads();

    for (int i = 0; i < 16; i++) {
        if (i < 15) {
            const float* pa = ga + (i + 1) * 32;
            const float* pb = gb + (i + 1) * 32;
#pragma unroll
            for (int p = 0; p < 8; p++) { fa[p] = *(const float4*)(pa + 4 * p); fb[p] = *(const float4*)(pb + 4 * p); }
        }
        const float* A = sm + (i & 1) * 2 * 128 * GP;
        const float* B = A + 128 * GP;
#pragma unroll
        for (int s = 0; s < 4; s++) {
            uint32_t Af[4][4];
#pragma unroll
            for (int ma = 0; ma < 4; ma++) {
                float2 lo = *(const float2*)(A + offA0[ma] + 8 * s);
                float2 hi = *(const float2*)(A + offA1[ma] + 8 * s);
                Af[ma][0] = __float_as_uint(lo.x); Af[ma][1] = __float_as_uint(hi.x);
                Af[ma][2] = __float_as_uint(lo.y); Af[ma][3] = __float_as_uint(hi.y);
            }
#pragma unroll
            for (int nb = 0; nb < 8; nb++) {
                float2 bv = *(const float2*)(B + offB[nb] + 8 * s);
                uint32_t b0 = __float_as_uint(bv.x), b1 = __float_as_uint(bv.y);
#pragma unroll
                for (int ma = 0; ma < 4; ma++) mma8(acc[ma][nb], Af[ma], b0, b1);
            }
        }
        if (i < 15) store_chunk((i + 1) & 1);
        __syncthreads();
    }

#pragma unroll
    for (int ma = 0; ma < 4; ma++) {
#pragma unroll
        for (int nb = 0; nb < 8; nb++) {
            int r0 = bm + wm * 64 + ma * 16 + g;
            int cg = bn + wn * 64 + nb * 8 + 2 * th;
#pragma unroll
            for (int e = 0; e < 2; e++) {
                int rr = r0 + e * 8;
                float v0 = acc[ma][nb][2 * e], v1 = acc[ma][nb][2 * e + 1];
                if (mode == 0) {
                    int bb = rr >> 10, n = rr & 1023;
                    int which = cg >> 9, hh = (cg >> 6) & 7, dd = cg & 63;
                    size_t off = (((size_t)(bb * NH + hh)) * NSEQ + n) * HD + dd;
                    float2 o;
                    if (which == 0) {
                        o.x = __uint_as_float(f2tf(v0 * QK_SCALE));
                        o.y = __uint_as_float(f2tf(v1 * QK_SCALE));
                        *(float2*)(g_q + off) = o;
                    } else if (which == 1) {
                        o.x = __uint_as_float(f2tf(v0)); o.y = __uint_as_float(f2tf(v1));
                        *(float2*)(g_k + off) = o;
                    } else {
                        o.x = __uint_as_float(f2tf(v0)); o.y = __uint_as_float(f2tf(v1));
                        *(float2*)(g_v + off) = o;
                    }
                } else {
                    float2 bv = *(const float2*)(Bvec + cg);
                    float2 o; o.x = v0 + bv.x; o.y = v1 + bv.y;
                    *(float2*)(Out + (size_t)rr * 512 + cg) = o;
                }
            }
        }
    }
}

// ===========================================================================
// Flash attention, tf32 mma. Grid (8 qt, 8 h, 8 b), 256 threads, 8 warps.
// Warp = 16 q-rows x 64 kv. Vt transpose stores XOR-swizzled (conflict-free).
// ===========================================================================
#define AP 72
#define ATT_SMEM (2 * 64 * AP * 4)

__global__ __launch_bounds__(256) void attn_mma(const float* __restrict__ bias) {
    extern __shared__ float sm[];
    float* Ks = sm;
    float* Vt = sm + 64 * AP;

    const int qt = blockIdx.x, h = blockIdx.y, b = blockIdx.z;
    const int tid = threadIdx.x, wid = tid >> 5, lane = tid & 31;
    const int g = lane >> 2, th = lane & 3;

    const size_t bh = (size_t)(b * NH + h);
    const float* Kg = g_k + bh * NSEQ * HD;
    const float* Vg = g_v + bh * NSEQ * HD;

    const int qrow = qt * 128 + wid * 16 + g;
    const float* Q0 = g_q + (bh * NSEQ + qrow) * HD;
    const float* Q1 = Q0 + 8 * HD;
    uint32_t qa[8][4];
#pragma unroll
    for (int s = 0; s < 8; s++) {
        qa[s][0] = __float_as_uint(Q0[8 * s + th]);
        qa[s][1] = __float_as_uint(Q1[8 * s + th]);
        qa[s][2] = __float_as_uint(Q0[8 * s + th + 4]);
        qa[s][3] = __float_as_uint(Q1[8 * s + th + 4]);
    }

    float O[8][4];
#pragma unroll
    for (int na = 0; na < 8; na++)
#pragma unroll
        for (int q = 0; q < 4; q++) O[na][q] = 0.0f;
    float mrow[2] = {-INFINITY, -INFINITY};
    float lrow[2] = {0.0f, 0.0f};

    const int lr4 = tid >> 2;
    const int lc4 = (tid & 3) * 16;
    const int pk = (lr4 & ~7) | ((lr4 & 3) << 1) | ((lr4 >> 2) & 1);
    const int xo = (tid & 3) << 3;     // d-block XOR for Vt stores
    const int pkx = pk ^ xo;

    for (int t = 0; t < 16; t++) {
        __syncthreads();
        const float* kp = Kg + (size_t)(t * 64 + lr4) * 64 + lc4;
        const float* vp = Vg + (size_t)(t * 64 + lr4) * 64 + lc4;
#pragma unroll
        for (int p = 0; p < 4; p++) {
            int d0 = lc4 + 4 * p;
            float4 k4 = *(const float4*)(kp + 4 * p);
            int cb = (d0 & ~7) + ((d0 >> 2) & 1);
            float* kr = Ks + lr4 * AP + cb;
            kr[0] = k4.x; kr[2] = k4.y; kr[4] = k4.z; kr[6] = k4.w;
            float4 v4 = *(const float4*)(vp + 4 * p);
            Vt[(d0 + 0) * AP + pkx] = v4.x;
            Vt[(d0 + 1) * AP + pkx] = v4.y;
            Vt[(d0 + 2) * AP + pkx] = v4.z;
            Vt[(d0 + 3) * AP + pkx] = v4.w;
        }
        __syncthreads();

        float S[8][4];
#pragma unroll
        for (int na = 0; na < 8; na++)
#pragma unroll
            for (int q = 0; q < 4; q++) S[na][q] = 0.0f;
#pragma unroll
        for (int s = 0; s < 8; s++) {
#pragma unroll
            for (int na = 0; na < 8; na++) {
                float2 bv = *(float2*)&Ks[(na * 8 + g) * AP + 8 * s + 2 * th];
                mma8(S[na], qa[s], __float_as_uint(bv.x), __float_as_uint(bv.y));
            }
        }

        const float* bp0 = bias + ((size_t)h * NSEQ + qrow) * NSEQ + t * 64 + 2 * th;
        const float* bp1 = bp0 + 8 * NSEQ;
#pragma unroll
        for (int na = 0; na < 8; na++) {
            float2 b0v = *(const float2*)(bp0 + na * 8);
            float2 b1v = *(const float2*)(bp1 + na * 8);
            S[na][0] += b0v.x; S[na][1] += b0v.y;
            S[na][2] += b1v.x; S[na][3] += b1v.y;
        }

#pragma unroll
        for (int e = 0; e < 2; e++) {
            float mx = -INFINITY;
#pragma unroll
            for (int na = 0; na < 8; na++)
                mx = fmaxf(mx, fmaxf(S[na][2 * e], S[na][2 * e + 1]));
            mx = fmaxf(mx, __shfl_xor_sync(0xffffffffu, mx, 1));
            mx = fmaxf(mx, __shfl_xor_sync(0xffffffffu, mx, 2));
            float mn = fmaxf(mrow[e], mx);
            float al = __expf(mrow[e] - mn);
            mrow[e] = mn;
            float ls = 0.0f;
#pragma unroll
            for (int na = 0; na < 8; na++) {
                S[na][2 * e]     = __expf(S[na][2 * e] - mn);
                S[na][2 * e + 1] = __expf(S[na][2 * e + 1] - mn);
                ls += S[na][2 * e] + S[na][2 * e + 1];
            }
            ls += __shfl_xor_sync(0xffffffffu, ls, 1);
            ls += __shfl_xor_sync(0xffffffffu, ls, 2);
            lrow[e] = lrow[e] * al + ls;
#pragma unroll
            for (int na = 0; na < 8; na++) { O[na][2 * e] *= al; O[na][2 * e + 1] *= al; }
        }

#pragma unroll
        for (int na = 0; na < 8; na++)
#pragma unroll
            for (int q = 0; q < 4; q++) S[na][q] = __uint_as_float(f2tf(S[na][q]));

        const int src0 = (lane & ~3) | (th >> 1);
        const int src2 = src0 + 2;
        const bool odd = (th & 1);
#pragma unroll
        for (int s = 0; s < 8; s++) {
            float x0 = __shfl_sync(0xffffffffu, S[s][0], src0);
            float x1 = __shfl_sync(0xffffffffu, S[s][1], src0);
            float y0 = __shfl_sync(0xffffffffu, S[s][2], src0);
            float y1 = __shfl_sync(0xffffffffu, S[s][3], src0);
            float z0 = __shfl_sync(0xffffffffu, S[s][0], src2);
            float z1 = __shfl_sync(0xffffffffu, S[s][1], src2);
            float w0 = __shfl_sync(0xffffffffu, S[s][2], src2);
            float w1 = __shfl_sync(0xffffffffu, S[s][3], src2);
            uint32_t a[4];
            a[0] = __float_as_uint(odd ? x1 : x0);
            a[1] = __float_as_uint(odd ? y1 : y0);
            a[2] = __float_as_uint(odd ? z1 : z0);
            a[3] = __float_as_uint(odd ? w1 : w0);
#pragma unroll
            for (int na = 0; na < 8; na++) {
                float2 bv = *(float2*)&Vt[(na * 8 + g) * AP + ((8 * s) ^ ((na >> 1) << 3)) + 2 * th];
                mma8(O[na], a, __float_as_uint(bv.x), __float_as_uint(bv.y));
            }
        }
    }

    const float i0 = 1.0f / lrow[0];
    const float i1 = 1.0f / lrow[1];
    float* ob = g_attn + ((size_t)b * NSEQ + qrow) * DIMC + h * 64 + 2 * th;
#pragma unroll
    for (int na = 0; na < 8; na++) {
        float2 o0; o0.x = O[na][0] * i0; o0.y = O[na][1] * i0;
        *(float2*)(ob + na * 8) = o0;
        float2 o1; o1.x = O[na][2] * i1; o1.y = O[na][3] * i1;
        *(float2*)(ob + (size_t)8 * DIMC + na * 8) = o1;
    }
}

extern "C" void kernel_launch(void* const* d_in, const int* in_sizes, int n_in,
                              void* d_out, int out_size) {
    const float* x      = (const float*)d_in[0];
    const float* rpe    = (const float*)d_in[1];
    const float* qkv_w  = (const float*)d_in[2];
    const float* proj_w = (const float*)d_in[3];
    const float* proj_b = (const float*)d_in[4];
    float* out = (float*)d_out;

    cudaFuncSetAttribute(mma_gemm, cudaFuncAttributeMaxDynamicSharedMemorySize, GEMM_SMEM);
    mma_gemm<<<dim3(64, 12), 128, GEMM_SMEM>>>(x, qkv_w, nullptr, nullptr, 0);
    attn_mma<<<dim3(8, 8, 8), 256, ATT_SMEM>>>(rpe);
    mma_gemm<<<dim3(64, 4), 128, GEMM_SMEM>>>(nullptr, proj_w, proj_b, out, 1);
}